// round 5
// baseline (speedup 1.0000x reference)
#include <cuda_runtime.h>

// ---------------------------------------------------------------------------
// 2-layer LSTM, B=2048, T=2048, I=1, H=16.
// R5: gate-parallel decomposition. One CTA (64 threads, 2 warps) per batch;
// each thread owns ONE gate row (t = type*16+j) for both pipelined chains
// (P = layer0 step s+1, Q = layer1 step s). Gate->state reduction via SMEM
// float4 + 2 CTA barriers per superstep. 4096 warps -> 27.7 warps/SM.
// ---------------------------------------------------------------------------

static constexpr int B = 2048;
static constexpr int T = 2048;
static constexpr int H = 16;

static __device__ __forceinline__ unsigned long long fma2(unsigned long long a,
                                                          unsigned long long b,
                                                          unsigned long long c) {
    unsigned long long d;
    asm("fma.rn.f32x2 %0, %1, %2, %3;" : "=l"(d) : "l"(a), "l"(b), "l"(c));
    return d;
}
static __device__ __forceinline__ unsigned long long pk2(float a, float b) {
    unsigned long long r;
    asm("mov.b64 %0, {%1, %2};" : "=l"(r) : "f"(a), "f"(b));
    return r;
}
static __device__ __forceinline__ void unpk2(unsigned long long v, float& a, float& b) {
    asm("mov.b64 {%0, %1}, %2;" : "=f"(a), "=f"(b) : "l"(v));
}
static __device__ __forceinline__ float tanhA(float x) {
    float r; asm("tanh.approx.f32 %0, %1;" : "=f"(r) : "f"(x)); return r;
}

__global__ __launch_bounds__(64, 14)
void lstm2_kernel(const float* __restrict__ x,
                  const float* __restrict__ h0in,
                  const float* __restrict__ c0in,
                  const float* __restrict__ Wih0,
                  const float* __restrict__ Whh0,
                  const float* __restrict__ bih0,
                  const float* __restrict__ bhh0,
                  const float* __restrict__ Wih1,
                  const float* __restrict__ Whh1,
                  const float* __restrict__ bih1,
                  const float* __restrict__ bhh1,
                  float* __restrict__ out)
{
    __shared__ __align__(16) float pg[64];   // activated layer0 gates [j*4+type]
    __shared__ __align__(16) float qg[64];   // activated layer1 gates [j*4+type]
    __shared__ __align__(16) float h0s[16];  // h0(s)
    __shared__ __align__(16) float h1s[16];  // h1(s-1)

    const int t    = threadIdx.x;     // 0..63 == gate row
    const int b    = blockIdx.x;
    const int j    = t & 15;          // hidden unit
    const int type = t >> 4;          // 0:i 1:f 2:g 3:o
    const int gidx = (j << 2) | type; // smem slot

    // ---- weights: one row each of Whh0, Wih1, Whh1, packed f32x2 ----
    unsigned long long w0[8], wi[8], w1[8];
    const float2* Wh0v = reinterpret_cast<const float2*>(Whh0);
    const float2* Wi1v = reinterpret_cast<const float2*>(Wih1);
    const float2* Wh1v = reinterpret_cast<const float2*>(Whh1);
#pragma unroll
    for (int p = 0; p < 8; ++p) {
        float2 a = Wh0v[t * 8 + p]; w0[p] = pk2(a.x, a.y);
        float2 c = Wi1v[t * 8 + p]; wi[p] = pk2(c.x, c.y);
        float2 e = Wh1v[t * 8 + p]; w1[p] = pk2(e.x, e.y);
    }
    const unsigned long long pInit = pk2(bih0[t] + bhh0[t], 0.0f);
    const unsigned long long qInit = pk2(bih1[t] + bhh1[t], 0.0f);
    const float wx = Wih0[t];                 // I == 1
    const unsigned long long ONE2 = pk2(1.0f, 1.0f);

    // activation constants: gate 'g' (type==2) -> tanh(k=1,c=0); else sigmoid
    const float kAct = (type == 2) ? 1.0f : 0.5f;
    const float cAct = (type == 2) ? 0.0f : 0.5f;

    // ---- state: lanes 0..15 own (c0,h0)[j]; lanes 16..31 own (c1,h1)[j] ----
    float cv = 0.0f, hv = 0.0f;
    if (t < 16) {
        h0s[t] = h0in[b * H + t];
        cv     = c0in[b * H + t];
    } else if (t < 32) {
        const int jj = t - 16;
        h1s[jj] = h0in[B * H + b * H + jj];
        cv      = c0in[B * H + b * H + jj];
    }
    __syncthreads();

    const float* xrow = x + (size_t)b * T;
    float*       outp = out + (size_t)b * T * H + (t - 16);   // lanes 16..31

    // ======================= prologue: layer0 step 0 =======================
    {
        const float xv0 = __ldg(xrow);
        const ulonglong2* hp = reinterpret_cast<const ulonglong2*>(h0s);
        ulonglong2 u0 = hp[0], u1 = hp[1], u2 = hp[2], u3 = hp[3];
        unsigned long long pA = pInit, pA2 = 0ull;
        pA  = fma2(w0[0], u0.x, pA);   pA2 = fma2(w0[4], u2.x, pA2);
        pA  = fma2(w0[1], u0.y, pA);   pA2 = fma2(w0[5], u2.y, pA2);
        pA  = fma2(w0[2], u1.x, pA);   pA2 = fma2(w0[6], u3.x, pA2);
        pA  = fma2(w0[3], u1.y, pA);   pA2 = fma2(w0[7], u3.y, pA2);
        pA  = fma2(pA2, ONE2, pA);
        float lo, hi; unpk2(pA, lo, hi);
        const float praw = fmaf(xv0, wx, lo + hi);
        pg[gidx] = fmaf(kAct, tanhA(kAct * praw), cAct);
        __syncthreads();
        if (t < 16) {
            const float4 gv = reinterpret_cast<const float4*>(pg)[t];
            cv = fmaf(gv.y, cv, gv.x * gv.z);
            hv = gv.w * tanhA(cv);
            h0s[t] = hv;
        }
        __syncthreads();
    }

    float xv = __ldg(xrow + 1);   // x for layer0 step 1 (superstep 0)

    // ================= supersteps s = 0 .. T-2 =============================
    // P: layer0 step s+1 (h0s);  Q: layer1 step s (h0s, h1s)
    for (int s = 0; s < T - 1; ++s) {
        const ulonglong2* hp0 = reinterpret_cast<const ulonglong2*>(h0s);
        const ulonglong2* hp1 = reinterpret_cast<const ulonglong2*>(h1s);
        ulonglong2 u0 = hp0[0], u1 = hp0[1], u2 = hp0[2], u3 = hp0[3];
        ulonglong2 v0 = hp1[0], v1 = hp1[1], v2 = hp1[2], v3 = hp1[3];

        const float xnext = __ldg(xrow + min(s + 2, T - 1));

        unsigned long long pA = pInit, pA2 = 0ull;
        unsigned long long qA = qInit, qB = 0ull;
        pA  = fma2(w0[0], u0.x, pA);   pA2 = fma2(w0[4], u2.x, pA2);
        qA  = fma2(wi[0], u0.x, qA);   qB  = fma2(w1[0], v0.x, qB);
        pA  = fma2(w0[1], u0.y, pA);   pA2 = fma2(w0[5], u2.y, pA2);
        qA  = fma2(wi[1], u0.y, qA);   qB  = fma2(w1[1], v0.y, qB);
        pA  = fma2(w0[2], u1.x, pA);   pA2 = fma2(w0[6], u3.x, pA2);
        qA  = fma2(wi[2], u1.x, qA);   qB  = fma2(w1[2], v1.x, qB);
        pA  = fma2(w0[3], u1.y, pA);   pA2 = fma2(w0[7], u3.y, pA2);
        qA  = fma2(wi[3], u1.y, qA);   qB  = fma2(w1[3], v1.y, qB);
        qA  = fma2(wi[4], u2.x, qA);   qB  = fma2(w1[4], v2.x, qB);
        qA  = fma2(wi[5], u2.y, qA);   qB  = fma2(w1[5], v2.y, qB);
        qA  = fma2(wi[6], u3.x, qA);   qB  = fma2(w1[6], v3.x, qB);
        qA  = fma2(wi[7], u3.y, qA);   qB  = fma2(w1[7], v3.y, qB);

        pA = fma2(pA2, ONE2, pA);
        qA = fma2(qB,  ONE2, qA);

        float plo, phi, qlo, qhi;
        unpk2(pA, plo, phi);
        unpk2(qA, qlo, qhi);
        const float praw = fmaf(xv, wx, plo + phi);
        const float qraw = qlo + qhi;

        pg[gidx] = fmaf(kAct, tanhA(kAct * praw), cAct);
        qg[gidx] = fmaf(kAct, tanhA(kAct * qraw), cAct);
        __syncthreads();

        if (t < 16) {
            const float4 gv = reinterpret_cast<const float4*>(pg)[t];
            cv = fmaf(gv.y, cv, gv.x * gv.z);
            hv = gv.w * tanhA(cv);
            h0s[t] = hv;
        } else if (t < 32) {
            const float4 gv = reinterpret_cast<const float4*>(qg)[t - 16];
            cv = fmaf(gv.y, cv, gv.x * gv.z);
            hv = gv.w * tanhA(cv);
            h1s[t - 16] = hv;
            outp[(size_t)s * H] = hv;         // out1[b, s, j]
        }
        xv = xnext;
        __syncthreads();
    }

    // =================== tail: layer1 step T-1 =============================
    {
        const ulonglong2* hp0 = reinterpret_cast<const ulonglong2*>(h0s);
        const ulonglong2* hp1 = reinterpret_cast<const ulonglong2*>(h1s);
        ulonglong2 u0 = hp0[0], u1 = hp0[1], u2 = hp0[2], u3 = hp0[3];
        ulonglong2 v0 = hp1[0], v1 = hp1[1], v2 = hp1[2], v3 = hp1[3];
        unsigned long long qA = qInit, qB = 0ull;
        qA = fma2(wi[0], u0.x, qA);   qB = fma2(w1[0], v0.x, qB);
        qA = fma2(wi[1], u0.y, qA);   qB = fma2(w1[1], v0.y, qB);
        qA = fma2(wi[2], u1.x, qA);   qB = fma2(w1[2], v1.x, qB);
        qA = fma2(wi[3], u1.y, qA);   qB = fma2(w1[3], v1.y, qB);
        qA = fma2(wi[4], u2.x, qA);   qB = fma2(w1[4], v2.x, qB);
        qA = fma2(wi[5], u2.y, qA);   qB = fma2(w1[5], v2.y, qB);
        qA = fma2(wi[6], u3.x, qA);   qB = fma2(w1[6], v3.x, qB);
        qA = fma2(wi[7], u3.y, qA);   qB = fma2(w1[7], v3.y, qB);
        qA = fma2(qB, ONE2, qA);
        float qlo, qhi; unpk2(qA, qlo, qhi);
        const float qraw = qlo + qhi;
        qg[gidx] = fmaf(kAct, tanhA(kAct * qraw), cAct);
        __syncthreads();
        if (t >= 16 && t < 32) {
            const float4 gv = reinterpret_cast<const float4*>(qg)[t - 16];
            cv = fmaf(gv.y, cv, gv.x * gv.z);
            hv = gv.w * tanhA(cv);
            outp[(size_t)(T - 1) * H] = hv;
        }
    }

    // final states: hN [2,B,H] then cN [2,B,H] appended after out1 [B,T,H]
    if (t < 16) {
        float* hN = out + (size_t)B * T * H;
        float* cN = hN + 2 * B * H;
        hN[b * H + t] = hv;
        cN[b * H + t] = cv;
    } else if (t < 32) {
        const int jj = t - 16;
        float* hN = out + (size_t)B * T * H;
        float* cN = hN + 2 * B * H;
        hN[B * H + b * H + jj] = hv;
        cN[B * H + b * H + jj] = cv;
    }
}

extern "C" void kernel_launch(void* const* d_in, const int* in_sizes, int n_in,
                              void* d_out, int out_size) {
    const float* x    = (const float*)d_in[0];
    const float* h0   = (const float*)d_in[1];
    const float* c0   = (const float*)d_in[2];
    const float* Wih0 = (const float*)d_in[3];
    const float* Whh0 = (const float*)d_in[4];
    const float* bih0 = (const float*)d_in[5];
    const float* bhh0 = (const float*)d_in[6];
    const float* Wih1 = (const float*)d_in[7];
    const float* Whh1 = (const float*)d_in[8];
    const float* bih1 = (const float*)d_in[9];
    const float* bhh1 = (const float*)d_in[10];
    float* out = (float*)d_out;

    lstm2_kernel<<<B, 64>>>(x, h0, c0, Wih0, Whh0, bih0, bhh0,
                            Wih1, Whh1, bih1, bhh1, out);
}